// round 10
// baseline (speedup 1.0000x reference)
#include <cuda_runtime.h>
#include <cstddef>
#include <cstdint>

#define NEGF (-1e20f)

constexpr int NA   = 512;
constexpr int NBC  = 1024;
constexpr int TPC  = 8;
constexpr int NT   = 128;          // 4 warps
constexpr int WIN  = 16;
constexpr int NWINS = 40;          // 640 steps >= 639
constexpr int E_NEG = -(1 << 28);

constexpr int F_F4 = 2 * WIN * NT * 2;   // double-buffered raw-W band (float4 units)
constexpr int O_F4 = WIN * NT * 2;       // output band (raw values)
constexpr size_t SMEM_B = (size_t)(F_F4 + O_F4) * 16 + (size_t)WIN * NT * 4 + 64;

__device__ __forceinline__ float p2(int d) {
    int k = max(d + 127, 0);
    return __int_as_float(k << 23);
}
__device__ __forceinline__ void cpa16(uint32_t dst, const void* src) {
    asm volatile("cp.async.cg.shared.global [%0], [%1], 16;" :: "r"(dst), "l"(src));
}

__global__ void __launch_bounds__(NT, 1)
dtw_sharedexp_kernel(const float* __restrict__ W, float* __restrict__ out) {
    extern __shared__ unsigned char sm[];
    float4* F = (float4*)sm;                                   // [2][WIN][NT][2]
    float4* O = F + F_F4;                                      // [WIN][NT][2] raw v
    int*    E = (int*)(O + O_F4);                              // [WIN][NT] e_base
    unsigned long long* bnd = (unsigned long long*)(E + WIN * NT); // [2][4]

    const int b = blockIdx.x, t = threadIdx.x, lane = t & 31, wd = t >> 5;
    const float* Wb = W + (size_t)b * NA * NBC;
    float* Ob = out + (size_t)b * (NA + 1) * (NBC + 1);
    const uint32_t Fs = (uint32_t)__cvta_generic_to_shared(F);

    // ---- edge outputs ----
    for (int k = t; k <= NBC; k += NT) Ob[k] = (k == 0) ? 0.0f : NEGF;
    for (int r = t + 1; r <= NA; r += NT) Ob[(size_t)r * (NBC + 1)] = NEGF;

    float tm[TPC];
    #pragma unroll
    for (int k = 0; k < TPC; ++k) tm[k] = 0.0f;
    int   te = E_NEG;                  // shared exponent of this thread's row values
    float pm = 0.0f; int pe = E_NEG;   // diag carry (left-in from step s-2)

    auto issue_fill = [&](int w) {
        if (w >= NWINS) return;
        const int S = WIN * w;
        const int p = w & 1;
        for (int m = wd; m < 143; m += 4) {
            int r = S - 127 + m;
            if ((unsigned)r < (unsigned)NA) {
                int tlo = max(S - r, 0), thi = min(S + 15 - r, 127);
                int tt = tlo + (lane >> 1), h = lane & 1;
                if (tt <= thi) {
                    int sg = (r + tt + 1) & (WIN - 1);
                    uint32_t dst = Fs + (uint32_t)((((p * WIN + sg) * NT + tt) * 2 + h) * 16);
                    cpa16(dst, Wb + (size_t)r * NBC + 8 * tt + 4 * h);
                }
            }
        }
        asm volatile("cp.async.commit_group;" ::: "memory");
    };
    auto flush_win = [&](int w) {
        const int Sp = WIN * w;
        for (int m = wd; m < 143; m += 4) {
            int i = Sp - 126 + m;
            if (i >= 1 && i <= NA) {
                int tlo = max(Sp + 1 - i, 0), thi = min(Sp + WIN - i, 127);
                int tt = tlo + (lane >> 1), h = lane & 1;
                if (tt <= thi) {
                    int sg = (i + tt) & (WIN - 1);
                    float4 v = O[(sg * NT + tt) * 2 + h];
                    float eb = (float)E[sg * NT + tt];
                    float* g = Ob + (size_t)i * (NBC + 1) + 8 * tt + 4 * h + 1;
                    g[0] = (__log2f(v.x) + eb) * 0.69314718056f;
                    g[1] = (__log2f(v.y) + eb) * 0.69314718056f;
                    g[2] = (__log2f(v.z) + eb) * 0.69314718056f;
                    g[3] = (__log2f(v.w) + eb) * 0.69314718056f;
                }
            }
        }
    };

    issue_fill(0);
    __syncthreads();

    for (int win = 0; win < NWINS; ++win) {
        const int S = WIN * win;
        asm volatile("cp.async.wait_group 0;" ::: "memory");
        __syncthreads();
        issue_fill(win + 1);
        if (win > 0) flush_win(win - 1);
        __syncthreads();

        #pragma unroll 1
        for (int q = 1; q <= WIN; ++q) {
            const int s = S + q;
            const int i = s - t;
            const bool act = (unsigned)(i - 1) < (unsigned)NA;

            float lvm = __shfl_up_sync(0xFFFFFFFFu, tm[TPC - 1], 1);
            int   lve = __shfl_up_sync(0xFFFFFFFFu, te, 1);
            if (lane == 0 && wd > 0) {
                unsigned long long pk = bnd[(s & 1) * 4 + wd - 1];
                lvm = __uint_as_float((unsigned)pk);
                lve = (int)(pk >> 32);
            }
            if (t == 0) { lvm = 0.0f; lve = E_NEG; }

            float dm = pm; int de = pe;
            if (i == 1) { dm = (t == 0) ? 1.0f : 0.0f; de = (t == 0) ? 0 : E_NEG; }
            pm = lvm; pe = lve;

            if (act) {
                const int sg = s & (WIN - 1);
                const int base = ((win & 1) * WIN + sg) * NT + t;
                float4 fA = F[base * 2];
                float4 fB = F[base * 2 + 1];
                float wv[TPC] = {fA.x, fA.y, fA.z, fA.w, fB.x, fB.y, fB.z, fB.w};

                int e_base = max(te, max(lve, de));
                float pt = p2(te  - e_base);
                float pl = p2(lve - e_base);
                float pd = p2(de  - e_base);

                float v[TPC];
                float leftm = fmaf(tm[0], pt, fmaf(dm, pd, lvm * pl));
                v[0] = fmaxf(leftm * __expf(wv[0]), 1e-35f);
                leftm = v[0];
                #pragma unroll
                for (int k = 1; k < TPC; ++k) {
                    float sk = fmaf(tm[k] + tm[k - 1], pt, leftm);
                    v[k] = fmaxf(sk * __expf(wv[k]), 1e-35f);
                    leftm = v[k];
                }

                int ob = (sg * NT + t) * 2;
                O[ob]     = make_float4(v[0], v[1], v[2], v[3]);
                O[ob + 1] = make_float4(v[4], v[5], v[6], v[7]);
                E[sg * NT + t] = e_base;

                // per-step renorm: one shared exponent for the 8 new values
                float vmax = fmaxf(fmaxf(fmaxf(v[0], v[1]), fmaxf(v[2], v[3])),
                                   fmaxf(fmaxf(v[4], v[5]), fmaxf(v[6], v[7])));
                int sh = (__float_as_int(vmax) >> 23) - 127;
                float sc = p2(-sh);
                #pragma unroll
                for (int k = 0; k < TPC; ++k) tm[k] = v[k] * sc;
                te = e_base + sh;

                if (lane == 31)
                    bnd[((s + 1) & 1) * 4 + wd] =
                        ((unsigned long long)(unsigned)te << 32) |
                        (unsigned long long)__float_as_uint(tm[TPC - 1]);
            }
            __syncthreads();
        }
    }

    flush_win(NWINS - 1);
}

extern "C" void kernel_launch(void* const* d_in, const int* in_sizes, int n_in,
                              void* d_out, int out_size) {
    const float* W = (const float*)d_in[0];
    float* out = (float*)d_out;
    cudaFuncSetAttribute(dtw_sharedexp_kernel,
                         cudaFuncAttributeMaxDynamicSharedMemorySize,
                         (int)SMEM_B);
    dtw_sharedexp_kernel<<<32, NT, SMEM_B>>>(W, out);
}